// round 1
// baseline (speedup 1.0000x reference)
#include <cuda_runtime.h>
#include <math.h>

// ---------------------------------------------------------------------------
// Problem constants
// ---------------------------------------------------------------------------
#define Bb 4
#define Tt 24
#define Hh 32
#define Ww 32
#define Dd 128
#define NPOS_PER_B (Tt*Hh*Ww)        // 24576
#define NPOS_TOTAL (Bb*NPOS_PER_B)   // 98304
#define N_CONV 5
#define NUM_FREQS 12
#define N_EXPERTS 7
#define BN_EPS 1e-5f
#define COMBINE_EPS 2.220446049250313e-16f

// ---------------------------------------------------------------------------
// Device scratch (no allocations allowed)
// ---------------------------------------------------------------------------
__device__ float g_buf0[96*16*16*128];   // ping
__device__ float g_buf1[96*8*8*128];     // pong
__device__ float g_wT[N_CONV*512*128];   // conv weights as [layer][k=tap*128+ci][co]
__device__ float g_gates[Bb*2];
__device__ int   g_eidx [Bb*2];

// ---------------------------------------------------------------------------
// Conv weight transpose: wT[l][tap*128+ci][co] = conv_w[l][co][ci][tap]
// ---------------------------------------------------------------------------
__global__ void wtrans_kernel(const float* __restrict__ cw) {
    int idx = blockIdx.x * 256 + threadIdx.x;
    if (idx >= N_CONV*512*128) return;
    int l   = idx / (512*128);
    int rem = idx - l*512*128;
    int k   = rem >> 7;          // tap*128+ci
    int co  = rem & 127;
    int tap = k >> 7;
    int ci  = k & 127;
    g_wT[idx] = cw[((l*128 + co)*128 + ci)*4 + tap];
}

// ---------------------------------------------------------------------------
// Conv layer as patch-GEMM:  out[p][co] = leaky(bn(sum_k A[p][k]*B[k][co]))
// A[p][k] = in[n, 2y+ky, 2x+kx, ci]   (NHWC), k = (ky*2+kx)*128 + ci
// BM=32, BN=128, BK=16, 256 threads, 4x4 per thread.
// ---------------------------------------------------------------------------
__global__ __launch_bounds__(256)
void conv_gemm_kernel(const float* __restrict__ in, float* __restrict__ out,
                      int Si, int So,
                      const float* __restrict__ wT,
                      const float* __restrict__ cb,
                      const float* __restrict__ gma,
                      const float* __restrict__ bta,
                      const float* __restrict__ mu,
                      const float* __restrict__ var) {
    __shared__ float As[32][17];
    __shared__ float Bs[16][128];
    __shared__ int   rowOff[32][4];

    const int tid = threadIdx.x;
    const int pm0 = blockIdx.x * 32;

    if (tid < 32) {
        int p   = pm0 + tid;
        int sq  = So * So;
        int n   = p / sq;
        int rem = p - n*sq;
        int y   = rem / So;
        int xx  = rem - y*So;
        #pragma unroll
        for (int tap = 0; tap < 4; ++tap) {
            int ky = tap >> 1, kx = tap & 1;
            rowOff[tid][tap] = ((n*Si + 2*y + ky)*Si + (2*xx + kx)) * 128;
        }
    }
    __syncthreads();

    float acc[4][4];
    #pragma unroll
    for (int i = 0; i < 4; ++i)
        #pragma unroll
        for (int j = 0; j < 4; ++j) acc[i][j] = 0.f;

    const int rowb = (tid >> 5) * 4;   // 8 row groups
    const int colb = (tid & 31) * 4;   // 32 col groups

    for (int k0 = 0; k0 < 512; k0 += 16) {
        const int tap    = k0 >> 7;
        const int cibase = k0 & 127;
        // A tile: 32x16
        #pragma unroll
        for (int j = 0; j < 2; ++j) {
            int idx = tid + j*256;
            int row = idx >> 4, kk = idx & 15;
            As[row][kk] = in[rowOff[row][tap] + cibase + kk];
        }
        // B tile: 16x128
        #pragma unroll
        for (int j = 0; j < 8; ++j) {
            int idx = tid + j*256;
            int kk = idx >> 7, co = idx & 127;
            Bs[kk][co] = wT[(k0 + kk)*128 + co];
        }
        __syncthreads();
        #pragma unroll
        for (int kk = 0; kk < 16; ++kk) {
            float a0 = As[rowb+0][kk];
            float a1 = As[rowb+1][kk];
            float a2 = As[rowb+2][kk];
            float a3 = As[rowb+3][kk];
            float4 bv = *(const float4*)&Bs[kk][colb];
            acc[0][0] += a0*bv.x; acc[0][1] += a0*bv.y; acc[0][2] += a0*bv.z; acc[0][3] += a0*bv.w;
            acc[1][0] += a1*bv.x; acc[1][1] += a1*bv.y; acc[1][2] += a1*bv.z; acc[1][3] += a1*bv.w;
            acc[2][0] += a2*bv.x; acc[2][1] += a2*bv.y; acc[2][2] += a2*bv.z; acc[2][3] += a2*bv.w;
            acc[3][0] += a3*bv.x; acc[3][1] += a3*bv.y; acc[3][2] += a3*bv.z; acc[3][3] += a3*bv.w;
        }
        __syncthreads();
    }

    // fused bias + BN + leaky, vectorized store
    float aC[4], cC[4];
    #pragma unroll
    for (int j = 0; j < 4; ++j) {
        int c = colb + j;
        aC[j] = gma[c] * rsqrtf(var[c] + BN_EPS);
        cC[j] = aC[j] * (cb[c] - mu[c]) + bta[c];
    }
    #pragma unroll
    for (int i = 0; i < 4; ++i) {
        float4 o;
        float v;
        v = acc[i][0]*aC[0] + cC[0]; o.x = v > 0.f ? v : 0.2f*v;
        v = acc[i][1]*aC[1] + cC[1]; o.y = v > 0.f ? v : 0.2f*v;
        v = acc[i][2]*aC[2] + cC[2]; o.z = v > 0.f ? v : 0.2f*v;
        v = acc[i][3]*aC[3] + cC[3]; o.w = v > 0.f ? v : 0.2f*v;
        *(float4*)&out[(pm0 + rowb + i)*128 + colb] = o;
    }
}

// ---------------------------------------------------------------------------
// Gates: fuse dot + rDFT(24, ortho, bins 1..12) + logits + top-2 softmax
// Single block, 128 threads.
// ---------------------------------------------------------------------------
__global__ void gates_kernel(const float* __restrict__ zf,     // [96][128]
                             const float* __restrict__ fw,     // [128]
                             const float* __restrict__ fb,     // [1]
                             const float* __restrict__ wg) {   // [12][7]
    __shared__ float s_s[96];
    __shared__ float s_amp[Bb][NUM_FREQS];
    __shared__ float s_log[Bb][N_EXPERTS];

    const int tid  = threadIdx.x;
    const int lane = tid & 31;
    const int warp = tid >> 5;

    // s[r] = dot(zf[r], fuse_w) + fuse_b
    for (int r = warp; r < 96; r += 4) {
        float v = zf[r*128 + lane       ] * fw[lane]
                + zf[r*128 + lane + 32  ] * fw[lane + 32]
                + zf[r*128 + lane + 64  ] * fw[lane + 64]
                + zf[r*128 + lane + 96  ] * fw[lane + 96];
        #pragma unroll
        for (int off = 16; off; off >>= 1)
            v += __shfl_down_sync(0xffffffffu, v, off);
        if (lane == 0) s_s[r] = v + fb[0];
    }
    __syncthreads();

    // rDFT bins 1..12, ortho norm (exact mod-24 phase reduction)
    if (tid < Bb*NUM_FREQS) {
        int b = tid / NUM_FREQS;
        int k = tid % NUM_FREQS + 1;
        float re = 0.f, im = 0.f;
        #pragma unroll
        for (int t = 0; t < Tt; ++t) {
            int m = (k * t) % 24;
            float ang = -(float)M_PI * (float)m / 12.f;
            float sv, cv;
            sincosf(ang, &sv, &cv);
            float x = s_s[b*Tt + t];
            re += x * cv;
            im += x * sv;
        }
        s_amp[b][k-1] = sqrtf(re*re + im*im) * 0.2041241452319315f; // 1/sqrt(24)
    }
    __syncthreads();

    // logits = amp @ w_gate
    if (tid < Bb*N_EXPERTS) {
        int b = tid / N_EXPERTS;
        int e = tid % N_EXPERTS;
        float l = 0.f;
        #pragma unroll
        for (int k = 0; k < NUM_FREQS; ++k)
            l += s_amp[b][k] * wg[k*N_EXPERTS + e];
        s_log[b][e] = l;
    }
    __syncthreads();

    // top-2 + softmax per batch
    if (tid < Bb) {
        int b = tid;
        int i1 = 0; float v1 = s_log[b][0];
        #pragma unroll
        for (int e = 1; e < N_EXPERTS; ++e)
            if (s_log[b][e] > v1) { v1 = s_log[b][e]; i1 = e; }
        int i2 = -1; float v2 = -INFINITY;
        #pragma unroll
        for (int e = 0; e < N_EXPERTS; ++e)
            if (e != i1 && s_log[b][e] > v2) { v2 = s_log[b][e]; i2 = e; }
        float e1 = expf(v2 - v1);          // v1 >= v2 -> stable
        float den = 1.f + e1;
        g_gates[b*2 + 0] = 1.f / den;
        g_gates[b*2 + 1] = e1 / den;
        g_eidx [b*2 + 0] = i1;
        g_eidx [b*2 + 1] = i2;
    }
}

// ---------------------------------------------------------------------------
// Main MoE path: for each position p (64-row tile), both selected experts,
// out = log(g0*exp(x@W_e0+b_e0) + g1*exp(x@W_e1+b_e1))
// BM=64, BN=64 (grid.y=2 halves of f), BK=16, 256 threads, 4x4 per thread.
// A tile resident in smem across both experts.
// ---------------------------------------------------------------------------
__global__ __launch_bounds__(256)
void moe_main_kernel(const float* __restrict__ x,
                     const float* __restrict__ ew,   // [7][128][128]
                     const float* __restrict__ eb,   // [7][128]
                     float* __restrict__ out) {
    __shared__ float As[64][129];
    __shared__ float Bs[16][64];

    const int tid = threadIdx.x;
    const int pm0 = blockIdx.x * 64;
    const int f0  = blockIdx.y * 64;
    const int b   = pm0 / NPOS_PER_B;

    // load full A tile (64 x 128) once
    #pragma unroll
    for (int j = 0; j < 32; ++j) {
        int idx = tid + j*256;
        int row = idx >> 7, c = idx & 127;
        As[row][c] = x[(pm0 + row)*128 + c];
    }
    __syncthreads();

    const int rowb = (tid >> 4) * 4;   // 16 row groups
    const int colb = (tid & 15) * 4;   // 16 col groups

    float comb[4][4];
    #pragma unroll
    for (int i = 0; i < 4; ++i)
        #pragma unroll
        for (int j = 0; j < 4; ++j) comb[i][j] = 0.f;

    #pragma unroll
    for (int s = 0; s < 2; ++s) {
        const int   e = g_eidx[b*2 + s];
        const float g = g_gates[b*2 + s];
        const float* W = ew + e*128*128 + f0;

        float acc[4][4];
        #pragma unroll
        for (int i = 0; i < 4; ++i)
            #pragma unroll
            for (int j = 0; j < 4; ++j) acc[i][j] = 0.f;

        for (int k0 = 0; k0 < 128; k0 += 16) {
            __syncthreads();
            #pragma unroll
            for (int j = 0; j < 4; ++j) {
                int idx = tid + j*256;
                int kk = idx >> 6, co = idx & 63;
                Bs[kk][co] = W[(k0 + kk)*128 + co];
            }
            __syncthreads();
            #pragma unroll
            for (int kk = 0; kk < 16; ++kk) {
                int k = k0 + kk;
                float a0 = As[rowb+0][k];
                float a1 = As[rowb+1][k];
                float a2 = As[rowb+2][k];
                float a3 = As[rowb+3][k];
                float4 bv = *(const float4*)&Bs[kk][colb];
                acc[0][0] += a0*bv.x; acc[0][1] += a0*bv.y; acc[0][2] += a0*bv.z; acc[0][3] += a0*bv.w;
                acc[1][0] += a1*bv.x; acc[1][1] += a1*bv.y; acc[1][2] += a1*bv.z; acc[1][3] += a1*bv.w;
                acc[2][0] += a2*bv.x; acc[2][1] += a2*bv.y; acc[2][2] += a2*bv.z; acc[2][3] += a2*bv.w;
                acc[3][0] += a3*bv.x; acc[3][1] += a3*bv.y; acc[3][2] += a3*bv.z; acc[3][3] += a3*bv.w;
            }
        }
        #pragma unroll
        for (int j = 0; j < 4; ++j) {
            float bias = eb[e*128 + f0 + colb + j];
            #pragma unroll
            for (int i = 0; i < 4; ++i)
                comb[i][j] += g * expf(acc[i][j] + bias);
        }
    }

    #pragma unroll
    for (int i = 0; i < 4; ++i) {
        float4 o;
        float c;
        c = comb[i][0]; if (c == 0.f) c = COMBINE_EPS; o.x = logf(c);
        c = comb[i][1]; if (c == 0.f) c = COMBINE_EPS; o.y = logf(c);
        c = comb[i][2]; if (c == 0.f) c = COMBINE_EPS; o.z = logf(c);
        c = comb[i][3]; if (c == 0.f) c = COMBINE_EPS; o.w = logf(c);
        *(float4*)&out[(pm0 + rowb + i)*128 + f0 + colb] = o;
    }
}

// ---------------------------------------------------------------------------
// Launch
// ---------------------------------------------------------------------------
extern "C" void kernel_launch(void* const* d_in, const int* in_sizes, int n_in,
                              void* d_out, int out_size) {
    const float* x        = (const float*)d_in[0];
    const float* conv_w   = (const float*)d_in[1];
    const float* conv_b   = (const float*)d_in[2];
    const float* bn_gamma = (const float*)d_in[3];
    const float* bn_beta  = (const float*)d_in[4];
    const float* bn_mean  = (const float*)d_in[5];
    const float* bn_var   = (const float*)d_in[6];
    const float* fuse_w   = (const float*)d_in[7];
    const float* fuse_b   = (const float*)d_in[8];
    const float* w_gate   = (const float*)d_in[9];
    const float* expert_w = (const float*)d_in[10];
    const float* expert_b = (const float*)d_in[11];
    float* out = (float*)d_out;

    float* buf0; cudaGetSymbolAddress((void**)&buf0, g_buf0);
    float* buf1; cudaGetSymbolAddress((void**)&buf1, g_buf1);
    float* wT;   cudaGetSymbolAddress((void**)&wT,   g_wT);

    // conv weight transpose
    wtrans_kernel<<<(N_CONV*512*128 + 255)/256, 256>>>(conv_w);

    // 5 conv layers (NHWC, ping-pong)
    const float* src = x;
    float*       dst = buf0;
    int Si = 32;
    for (int l = 0; l < N_CONV; ++l) {
        int So = Si >> 1;
        int M  = 96 * So * So;
        conv_gemm_kernel<<<M/32, 256>>>(src, dst, Si, So,
                                        wT + l*512*128,
                                        conv_b   + l*128,
                                        bn_gamma + l*128,
                                        bn_beta  + l*128,
                                        bn_mean  + l*128,
                                        bn_var   + l*128);
        // rotate buffers: x->buf0->buf1->buf0->buf1->buf0
        src = dst;
        dst = (dst == buf0) ? buf1 : buf0;
        Si = So;
    }
    // final conv output is in buf0 (layers land: buf0,buf1,buf0,buf1,buf0)

    gates_kernel<<<1, 128>>>(buf0, fuse_w, fuse_b, w_gate);

    dim3 grid(NPOS_TOTAL/64, 2);
    moe_main_kernel<<<grid, 256>>>(x, expert_w, expert_b, out);
}

// round 4
// speedup vs baseline: 1.2390x; 1.2390x over previous
#include <cuda_runtime.h>
#include <cuda_bf16.h>
#include <math.h>
#include <stdint.h>

// ---------------------------------------------------------------------------
// Problem constants
// ---------------------------------------------------------------------------
#define Bb 4
#define Tt 24
#define Hh 32
#define Ww 32
#define Dd 128
#define NPOS_PER_B (Tt*Hh*Ww)        // 24576
#define NPOS_TOTAL (Bb*NPOS_PER_B)   // 98304
#define N_CONV 5
#define NUM_FREQS 12
#define N_EXPERTS 7
#define BN_EPS 1e-5f
#define COMBINE_EPS 2.220446049250313e-16f

// ---------------------------------------------------------------------------
// Device scratch (no allocations allowed)
// ---------------------------------------------------------------------------
__device__ float g_buf0[96*16*16*128];   // ping
__device__ float g_buf1[96*8*8*128];     // pong
__device__ float g_wT[N_CONV*512*128];   // conv weights as [layer][k=tap*128+ci][co]
__device__ float g_gates[Bb*2];
__device__ int   g_eidx [Bb*2];
// split-bf16 expert weights, transposed: [e][f][d]
__device__ __align__(16) __nv_bfloat16 g_wtHi[N_EXPERTS*128*128];
__device__ __align__(16) __nv_bfloat16 g_wtLo[N_EXPERTS*128*128];

__device__ __forceinline__ uint32_t pack_bf16(float a, float b) {
    uint32_t lo = (uint32_t)__bfloat16_as_ushort(__float2bfloat16(a));
    uint32_t hi = (uint32_t)__bfloat16_as_ushort(__float2bfloat16(b));
    return lo | (hi << 16);
}

// mma.sync m16n8k16 bf16 (baseline PTX, works at compute_103)
__device__ __forceinline__ void mma16816(float* d, const uint32_t* a,
                                         uint32_t b0, uint32_t b1) {
    asm volatile(
        "mma.sync.aligned.m16n8k16.row.col.f32.bf16.bf16.f32 "
        "{%0,%1,%2,%3}, {%4,%5,%6,%7}, {%8,%9}, {%0,%1,%2,%3};"
        : "+f"(d[0]), "+f"(d[1]), "+f"(d[2]), "+f"(d[3])
        : "r"(a[0]), "r"(a[1]), "r"(a[2]), "r"(a[3]), "r"(b0), "r"(b1));
}

// ---------------------------------------------------------------------------
// Conv weight transpose: wT[l][tap*128+ci][co] = conv_w[l][co][ci][tap]
// ---------------------------------------------------------------------------
__global__ void wtrans_kernel(const float* __restrict__ cw) {
    int idx = blockIdx.x * 256 + threadIdx.x;
    if (idx >= N_CONV*512*128) return;
    int l   = idx / (512*128);
    int rem = idx - l*512*128;
    int k   = rem >> 7;
    int co  = rem & 127;
    int tap = k >> 7;
    int ci  = k & 127;
    g_wT[idx] = cw[((l*128 + co)*128 + ci)*4 + tap];
}

// ---------------------------------------------------------------------------
// Expert weight split + transpose: g_wtHi/Lo[e][f][d] = split(expert_w[e][d][f])
// ---------------------------------------------------------------------------
__global__ void wsplit_kernel(const float* __restrict__ ew) {
    int idx = blockIdx.x * 256 + threadIdx.x;
    if (idx >= N_EXPERTS*128*128) return;
    int e = idx / 16384;
    int rem = idx - e*16384;
    int d = rem >> 7;
    int f = rem & 127;
    float v = ew[idx];
    __nv_bfloat16 h = __float2bfloat16(v);
    float lo = v - __bfloat162float(h);
    g_wtHi[e*16384 + f*128 + d] = h;
    g_wtLo[e*16384 + f*128 + d] = __float2bfloat16(lo);
}

// ---------------------------------------------------------------------------
// Conv layer as patch-GEMM with register-prefetch double buffering.
// ---------------------------------------------------------------------------
__global__ __launch_bounds__(256)
void conv_gemm_kernel(const float* __restrict__ in, float* __restrict__ out,
                      int Si, int So,
                      const float* __restrict__ wT,
                      const float* __restrict__ cb,
                      const float* __restrict__ gma,
                      const float* __restrict__ bta,
                      const float* __restrict__ mu,
                      const float* __restrict__ var) {
    __shared__ float As[2][32][17];
    __shared__ float Bs[2][16][128];
    __shared__ int   rowOff[32][4];

    const int tid = threadIdx.x;
    const int pm0 = blockIdx.x * 32;

    if (tid < 32) {
        int p   = pm0 + tid;
        int sq  = So * So;
        int n   = p / sq;
        int rem = p - n*sq;
        int y   = rem / So;
        int xx  = rem - y*So;
        #pragma unroll
        for (int tap = 0; tap < 4; ++tap) {
            int ky = tap >> 1, kx = tap & 1;
            rowOff[tid][tap] = ((n*Si + 2*y + ky)*Si + (2*xx + kx)) * 128;
        }
    }
    __syncthreads();

    float acc[4][4];
    #pragma unroll
    for (int i = 0; i < 4; ++i)
        #pragma unroll
        for (int j = 0; j < 4; ++j) acc[i][j] = 0.f;

    const int rowb = (tid >> 5) * 4;
    const int colb = (tid & 31) * 4;

    float nA[2], nB[8];
    #pragma unroll
    for (int j = 0; j < 2; ++j) {
        int idx = tid + j*256;
        nA[j] = in[rowOff[idx >> 4][0] + (idx & 15)];
    }
    #pragma unroll
    for (int j = 0; j < 8; ++j) {
        int idx = tid + j*256;
        nB[j] = wT[(idx >> 7)*128 + (idx & 127)];
    }
    #pragma unroll
    for (int j = 0; j < 2; ++j) { int idx = tid + j*256; As[0][idx>>4][idx&15] = nA[j]; }
    #pragma unroll
    for (int j = 0; j < 8; ++j) { int idx = tid + j*256; Bs[0][idx>>7][idx&127] = nB[j]; }
    __syncthreads();

    int cur = 0;
    for (int k0 = 0; k0 < 512; k0 += 16) {
        const bool hasNext = (k0 + 16 < 512);
        if (hasNext) {
            const int kn  = k0 + 16;
            const int tap = kn >> 7;
            const int cib = kn & 127;
            #pragma unroll
            for (int j = 0; j < 2; ++j) {
                int idx = tid + j*256;
                nA[j] = in[rowOff[idx >> 4][tap] + cib + (idx & 15)];
            }
            #pragma unroll
            for (int j = 0; j < 8; ++j) {
                int idx = tid + j*256;
                nB[j] = wT[(kn + (idx >> 7))*128 + (idx & 127)];
            }
        }
        #pragma unroll
        for (int kk = 0; kk < 16; ++kk) {
            float a0 = As[cur][rowb+0][kk];
            float a1 = As[cur][rowb+1][kk];
            float a2 = As[cur][rowb+2][kk];
            float a3 = As[cur][rowb+3][kk];
            float4 bv = *(const float4*)&Bs[cur][kk][colb];
            acc[0][0] += a0*bv.x; acc[0][1] += a0*bv.y; acc[0][2] += a0*bv.z; acc[0][3] += a0*bv.w;
            acc[1][0] += a1*bv.x; acc[1][1] += a1*bv.y; acc[1][2] += a1*bv.z; acc[1][3] += a1*bv.w;
            acc[2][0] += a2*bv.x; acc[2][1] += a2*bv.y; acc[2][2] += a2*bv.z; acc[2][3] += a2*bv.w;
            acc[3][0] += a3*bv.x; acc[3][1] += a3*bv.y; acc[3][2] += a3*bv.z; acc[3][3] += a3*bv.w;
        }
        if (hasNext) {
            int nxt = cur ^ 1;
            #pragma unroll
            for (int j = 0; j < 2; ++j) { int idx = tid + j*256; As[nxt][idx>>4][idx&15] = nA[j]; }
            #pragma unroll
            for (int j = 0; j < 8; ++j) { int idx = tid + j*256; Bs[nxt][idx>>7][idx&127] = nB[j]; }
            __syncthreads();
            cur = nxt;
        }
    }

    float aC[4], cC[4];
    #pragma unroll
    for (int j = 0; j < 4; ++j) {
        int c = colb + j;
        aC[j] = gma[c] * rsqrtf(var[c] + BN_EPS);
        cC[j] = aC[j] * (cb[c] - mu[c]) + bta[c];
    }
    #pragma unroll
    for (int i = 0; i < 4; ++i) {
        float4 o;
        float v;
        v = acc[i][0]*aC[0] + cC[0]; o.x = v > 0.f ? v : 0.2f*v;
        v = acc[i][1]*aC[1] + cC[1]; o.y = v > 0.f ? v : 0.2f*v;
        v = acc[i][2]*aC[2] + cC[2]; o.z = v > 0.f ? v : 0.2f*v;
        v = acc[i][3]*aC[3] + cC[3]; o.w = v > 0.f ? v : 0.2f*v;
        *(float4*)&out[(pm0 + rowb + i)*128 + colb] = o;
    }
}

// ---------------------------------------------------------------------------
// Gates kernel
// ---------------------------------------------------------------------------
__global__ void gates_kernel(const float* __restrict__ zf,
                             const float* __restrict__ fw,
                             const float* __restrict__ fb,
                             const float* __restrict__ wg) {
    __shared__ float s_s[96];
    __shared__ float s_amp[Bb][NUM_FREQS];
    __shared__ float s_log[Bb][N_EXPERTS];

    const int tid  = threadIdx.x;
    const int lane = tid & 31;
    const int warp = tid >> 5;

    for (int r = warp; r < 96; r += 4) {
        float v = zf[r*128 + lane       ] * fw[lane]
                + zf[r*128 + lane + 32  ] * fw[lane + 32]
                + zf[r*128 + lane + 64  ] * fw[lane + 64]
                + zf[r*128 + lane + 96  ] * fw[lane + 96];
        #pragma unroll
        for (int off = 16; off; off >>= 1)
            v += __shfl_down_sync(0xffffffffu, v, off);
        if (lane == 0) s_s[r] = v + fb[0];
    }
    __syncthreads();

    if (tid < Bb*NUM_FREQS) {
        int b = tid / NUM_FREQS;
        int k = tid % NUM_FREQS + 1;
        float re = 0.f, im = 0.f;
        #pragma unroll
        for (int t = 0; t < Tt; ++t) {
            int m = (k * t) % 24;
            float ang = -(float)M_PI * (float)m / 12.f;
            float sv, cv;
            sincosf(ang, &sv, &cv);
            float x = s_s[b*Tt + t];
            re += x * cv;
            im += x * sv;
        }
        s_amp[b][k-1] = sqrtf(re*re + im*im) * 0.2041241452319315f;
    }
    __syncthreads();

    if (tid < Bb*N_EXPERTS) {
        int b = tid / N_EXPERTS;
        int e = tid % N_EXPERTS;
        float l = 0.f;
        #pragma unroll
        for (int k = 0; k < NUM_FREQS; ++k)
            l += s_amp[b][k] * wg[k*N_EXPERTS + e];
        s_log[b][e] = l;
    }
    __syncthreads();

    if (tid < Bb) {
        int b = tid;
        int i1 = 0; float v1 = s_log[b][0];
        #pragma unroll
        for (int e = 1; e < N_EXPERTS; ++e)
            if (s_log[b][e] > v1) { v1 = s_log[b][e]; i1 = e; }
        int i2 = -1; float v2 = -INFINITY;
        #pragma unroll
        for (int e = 0; e < N_EXPERTS; ++e)
            if (e != i1 && s_log[b][e] > v2) { v2 = s_log[b][e]; i2 = e; }
        float e1 = expf(v2 - v1);
        float den = 1.f + e1;
        g_gates[b*2 + 0] = 1.f / den;
        g_gates[b*2 + 1] = e1 / den;
        g_eidx [b*2 + 0] = i1;
        g_eidx [b*2 + 1] = i2;
    }
}

// ---------------------------------------------------------------------------
// MoE main path via mma.sync bf16 (split hi/lo, 3 terms per expert).
// Per CTA: 64 rows x 128 f, 2 experts sequentially, 8 warps (2x4 warp grid),
// warp tile 32x32 = 2 m-tiles x 4 n-tiles of m16n8k16.
// A (hi+lo) and B (hi+lo, current expert) fully smem-resident, rows padded
// to 136 bf16 for conflict-free fragment LDS.
// Epilogue: comb += g*exp(acc+bias); out = log(comb). Single output write.
// ---------------------------------------------------------------------------
#define STR   136
#define SA_HI 0
#define SA_LO 17408
#define SB_HI 34816
#define SB_LO 69632
#define MOE_SMEM 104448

__global__ __launch_bounds__(256)
void moe_mma_kernel(const float* __restrict__ x,
                    const float* __restrict__ eb,
                    float* __restrict__ out) {
    extern __shared__ char dsm[];
    __nv_bfloat16* sAhi = (__nv_bfloat16*)(dsm + SA_HI);
    __nv_bfloat16* sAlo = (__nv_bfloat16*)(dsm + SA_LO);
    __nv_bfloat16* sBhi = (__nv_bfloat16*)(dsm + SB_HI);
    __nv_bfloat16* sBlo = (__nv_bfloat16*)(dsm + SB_LO);

    const int tid  = threadIdx.x;
    const int wid  = tid >> 5;
    const int lane = tid & 31;
    const int g    = lane >> 2;
    const int t    = lane & 3;
    const int warp_m = wid & 1;    // 2 row groups of 32
    const int warp_n = wid >> 1;   // 4 col groups of 32
    const int pm0  = blockIdx.x * 64;
    const int b    = pm0 / NPOS_PER_B;

    // --- A: load x fp32, split to hi/lo bf16 ---------------------------------
    #pragma unroll
    for (int j = 0; j < 8; ++j) {
        int i = tid + j*256;         // 2048 float4 total = 64 rows x 32 quads
        int r = i >> 5, q = i & 31;
        float4 v = *(const float4*)&x[(size_t)(pm0 + r)*128 + q*4];
        __nv_bfloat16 hx = __float2bfloat16(v.x);
        __nv_bfloat16 hy = __float2bfloat16(v.y);
        __nv_bfloat16 hz = __float2bfloat16(v.z);
        __nv_bfloat16 hw = __float2bfloat16(v.w);
        uint32_t h01 = (uint32_t)__bfloat16_as_ushort(hx) | ((uint32_t)__bfloat16_as_ushort(hy) << 16);
        uint32_t h23 = (uint32_t)__bfloat16_as_ushort(hz) | ((uint32_t)__bfloat16_as_ushort(hw) << 16);
        uint32_t l01 = pack_bf16(v.x - __bfloat162float(hx), v.y - __bfloat162float(hy));
        uint32_t l23 = pack_bf16(v.z - __bfloat162float(hz), v.w - __bfloat162float(hw));
        int off = r*STR + q*4;
        *(uint2*)&sAhi[off] = make_uint2(h01, h23);
        *(uint2*)&sAlo[off] = make_uint2(l01, l23);
    }

    float comb[2][4][4];
    #pragma unroll
    for (int mt = 0; mt < 2; ++mt)
        #pragma unroll
        for (int nt = 0; nt < 4; ++nt)
            #pragma unroll
            for (int j = 0; j < 4; ++j) comb[mt][nt][j] = 0.f;

    #pragma unroll
    for (int s = 0; s < 2; ++s) {
        const int   e  = g_eidx[b*2 + s];
        const float gv = g_gates[b*2 + s];

        // --- B: copy split bf16 expert weights into padded smem ---------------
        // 4096 uint4 total: 2 bufs x 128 rows x 16 uint4 (8 bf16 each)
        __syncthreads();   // (s==1: all warps done reading previous B; s==0: A visible)
        #pragma unroll
        for (int j = 0; j < 16; ++j) {
            int i   = tid + j*256;
            int buf = i >> 11;
            int rem = i & 2047;
            int n   = rem >> 4;
            int c   = rem & 15;
            const __nv_bfloat16* src = (buf ? g_wtLo : g_wtHi) + e*16384 + n*128 + c*8;
            uint4 v = *(const uint4*)src;
            __nv_bfloat16* dstb = buf ? sBlo : sBhi;
            *(uint4*)&dstb[n*STR + c*8] = v;
        }
        __syncthreads();

        float acc[2][4][4];
        #pragma unroll
        for (int mt = 0; mt < 2; ++mt)
            #pragma unroll
            for (int nt = 0; nt < 4; ++nt)
                #pragma unroll
                for (int j = 0; j < 4; ++j) acc[mt][nt][j] = 0.f;

        // --- 3 terms: Ah*Bh, Al*Bh, Ah*Bl -------------------------------------
        #pragma unroll
        for (int term = 0; term < 3; ++term) {
            const __nv_bfloat16* Ab = (term == 1) ? sAlo : sAhi;
            const __nv_bfloat16* Bbuf = (term == 2) ? sBlo : sBhi;
            #pragma unroll
            for (int ks = 0; ks < 8; ++ks) {
                const int k0 = ks*16;
                uint32_t af[2][4];
                #pragma unroll
                for (int mt = 0; mt < 2; ++mt) {
                    int r0 = warp_m*32 + mt*16 + g;
                    const __nv_bfloat16* ap = Ab + k0 + 2*t;
                    af[mt][0] = *(const uint32_t*)(ap + (size_t)r0*STR);
                    af[mt][1] = *(const uint32_t*)(ap + (size_t)(r0+8)*STR);
                    af[mt][2] = *(const uint32_t*)(ap + (size_t)r0*STR + 8);
                    af[mt][3] = *(const uint32_t*)(ap + (size_t)(r0+8)*STR + 8);
                }
                #pragma unroll
                for (int nt = 0; nt < 4; ++nt) {
                    int n = warp_n*32 + nt*8 + g;
                    const __nv_bfloat16* bp = Bbuf + (size_t)n*STR + k0 + 2*t;
                    uint32_t b0 = *(const uint32_t*)bp;
                    uint32_t b1 = *(const uint32_t*)(bp + 8);
                    mma16816(acc[0][nt], af[0], b0, b1);
                    mma16816(acc[1][nt], af[1], b0, b1);
                }
            }
        }

        // --- expert epilogue: comb += g * exp(acc + bias) ----------------------
        #pragma unroll
        for (int nt = 0; nt < 4; ++nt) {
            int col0 = warp_n*32 + nt*8 + 2*t;
            float b0v = eb[e*128 + col0];
            float b1v = eb[e*128 + col0 + 1];
            #pragma unroll
            for (int mt = 0; mt < 2; ++mt) {
                comb[mt][nt][0] += gv * expf(acc[mt][nt][0] + b0v);
                comb[mt][nt][1] += gv * expf(acc[mt][nt][1] + b1v);
                comb[mt][nt][2] += gv * expf(acc[mt][nt][2] + b0v);
                comb[mt][nt][3] += gv * expf(acc[mt][nt][3] + b1v);
            }
        }
    }

    // --- final: out = log(comb), vectorized 64-bit stores -----------------------
    #pragma unroll
    for (int mt = 0; mt < 2; ++mt) {
        int row = pm0 + warp_m*32 + mt*16 + g;
        #pragma unroll
        for (int nt = 0; nt < 4; ++nt) {
            int col = warp_n*32 + nt*8 + 2*t;
            float c0 = comb[mt][nt][0]; if (c0 == 0.f) c0 = COMBINE_EPS;
            float c1 = comb[mt][nt][1]; if (c1 == 0.f) c1 = COMBINE_EPS;
            float c2 = comb[mt][nt][2]; if (c2 == 0.f) c2 = COMBINE_EPS;
            float c3 = comb[mt][nt][3]; if (c3 == 0.f) c3 = COMBINE_EPS;
            float2 o0 = make_float2(logf(c0), logf(c1));
            float2 o1 = make_float2(logf(c2), logf(c3));
            *(float2*)&out[(size_t)row*128 + col]      = o0;
            *(float2*)&out[(size_t)(row+8)*128 + col]  = o1;
        }
    }
}

// ---------------------------------------------------------------------------
// Launch
// ---------------------------------------------------------------------------
extern "C" void kernel_launch(void* const* d_in, const int* in_sizes, int n_in,
                              void* d_out, int out_size) {
    const float* x        = (const float*)d_in[0];
    const float* conv_w   = (const float*)d_in[1];
    const float* conv_b   = (const float*)d_in[2];
    const float* bn_gamma = (const float*)d_in[3];
    const float* bn_beta  = (const float*)d_in[4];
    const float* bn_mean  = (const float*)d_in[5];
    const float* bn_var   = (const float*)d_in[6];
    const float* fuse_w   = (const float*)d_in[7];
    const float* fuse_b   = (const float*)d_in[8];
    const float* w_gate   = (const float*)d_in[9];
    const float* expert_w = (const float*)d_in[10];
    const float* expert_b = (const float*)d_in[11];
    float* out = (float*)d_out;

    float* buf0; cudaGetSymbolAddress((void**)&buf0, g_buf0);
    float* buf1; cudaGetSymbolAddress((void**)&buf1, g_buf1);
    float* wT;   cudaGetSymbolAddress((void**)&wT,   g_wT);

    cudaFuncSetAttribute(moe_mma_kernel,
                         cudaFuncAttributeMaxDynamicSharedMemorySize, MOE_SMEM);

    wtrans_kernel<<<(N_CONV*512*128 + 255)/256, 256>>>(conv_w);
    wsplit_kernel<<<(N_EXPERTS*128*128 + 255)/256, 256>>>(expert_w);

    const float* src = x;
    float*       dst = buf0;
    int Si = 32;
    for (int l = 0; l < N_CONV; ++l) {
        int So = Si >> 1;
        int M  = 96 * So * So;
        conv_gemm_kernel<<<M/32, 256>>>(src, dst, Si, So,
                                        wT + l*512*128,
                                        conv_b   + l*128,
                                        bn_gamma + l*128,
                                        bn_beta  + l*128,
                                        bn_mean  + l*128,
                                        bn_var   + l*128);
        src = dst;
        dst = (dst == buf0) ? buf1 : buf0;
        Si = So;
    }

    gates_kernel<<<1, 128>>>(buf0, fuse_w, fuse_b, w_gate);

    moe_mma_kernel<<<NPOS_TOTAL/64, 256, MOE_SMEM>>>(x, expert_b, out);
}

// round 5
// speedup vs baseline: 2.0393x; 1.6459x over previous
#include <cuda_runtime.h>
#include <cuda_bf16.h>
#include <math.h>
#include <stdint.h>

// ---------------------------------------------------------------------------
// Problem constants
// ---------------------------------------------------------------------------
#define Bb 4
#define Tt 24
#define Hh 32
#define Ww 32
#define Dd 128
#define NPOS_PER_B (Tt*Hh*Ww)        // 24576
#define NPOS_TOTAL (Bb*NPOS_PER_B)   // 98304
#define N_CONV 5
#define NUM_FREQS 12
#define N_EXPERTS 7
#define BN_EPS 1e-5f
#define COMBINE_EPS 2.220446049250313e-16f

// ---------------------------------------------------------------------------
// Device scratch (no allocations allowed)
// ---------------------------------------------------------------------------
__device__ __align__(16) __nv_bfloat16 g_xHi[NPOS_TOTAL*128];
__device__ __align__(16) __nv_bfloat16 g_xLo[NPOS_TOTAL*128];
__device__ __align__(16) __nv_bfloat16 g_aHi0[24576*128];
__device__ __align__(16) __nv_bfloat16 g_aLo0[24576*128];
__device__ __align__(16) __nv_bfloat16 g_aHi1[6144*128];
__device__ __align__(16) __nv_bfloat16 g_aLo1[6144*128];
__device__ __align__(16) __nv_bfloat16 g_cwHi[N_CONV*128*512];   // [l][co][k]
__device__ __align__(16) __nv_bfloat16 g_cwLo[N_CONV*128*512];
__device__ float g_gates[Bb*2];
__device__ int   g_eidx [Bb*2];
__device__ __align__(16) __nv_bfloat16 g_wtHi[N_EXPERTS*128*128]; // [e][f][d]
__device__ __align__(16) __nv_bfloat16 g_wtLo[N_EXPERTS*128*128];

__device__ __forceinline__ uint32_t pack_bf16(float a, float b) {
    uint32_t lo = (uint32_t)__bfloat16_as_ushort(__float2bfloat16(a));
    uint32_t hi = (uint32_t)__bfloat16_as_ushort(__float2bfloat16(b));
    return lo | (hi << 16);
}
__device__ __forceinline__ uint32_t smem_u32(const void* p) {
    uint32_t a;
    asm("{ .reg .u64 t; cvta.to.shared.u64 t, %1; cvt.u32.u64 %0, t; }"
        : "=r"(a) : "l"(p));
    return a;
}

// mma.sync m16n8k16 bf16 (baseline PTX, works at compute_103)
__device__ __forceinline__ void mma16816(float* d, const uint32_t* a,
                                         uint32_t b0, uint32_t b1) {
    asm volatile(
        "mma.sync.aligned.m16n8k16.row.col.f32.bf16.bf16.f32 "
        "{%0,%1,%2,%3}, {%4,%5,%6,%7}, {%8,%9}, {%0,%1,%2,%3};"
        : "+f"(d[0]), "+f"(d[1]), "+f"(d[2]), "+f"(d[3])
        : "r"(a[0]), "r"(a[1]), "r"(a[2]), "r"(a[3]), "r"(b0), "r"(b1));
}

#define CP_ASYNC16(dst, src) \
    asm volatile("cp.async.cg.shared.global [%0], [%1], 16;" :: "r"(dst), "l"(src))
#define CP_COMMIT() asm volatile("cp.async.commit_group;")
#define CP_WAIT(N)  asm volatile("cp.async.wait_group %0;" :: "n"(N))

// ---------------------------------------------------------------------------
// x split: fp32 -> hi/lo bf16
// ---------------------------------------------------------------------------
__global__ void xsplit_kernel(const float4* __restrict__ x) {
    int idx = blockIdx.x * 256 + threadIdx.x;      // 3,145,728 float4
    if (idx >= NPOS_TOTAL*32) return;
    float4 v = x[idx];
    __nv_bfloat16 hx = __float2bfloat16(v.x);
    __nv_bfloat16 hy = __float2bfloat16(v.y);
    __nv_bfloat16 hz = __float2bfloat16(v.z);
    __nv_bfloat16 hw = __float2bfloat16(v.w);
    uint2 h = make_uint2(
        (uint32_t)__bfloat16_as_ushort(hx) | ((uint32_t)__bfloat16_as_ushort(hy) << 16),
        (uint32_t)__bfloat16_as_ushort(hz) | ((uint32_t)__bfloat16_as_ushort(hw) << 16));
    uint2 l = make_uint2(
        pack_bf16(v.x - __bfloat162float(hx), v.y - __bfloat162float(hy)),
        pack_bf16(v.z - __bfloat162float(hz), v.w - __bfloat162float(hw)));
    ((uint2*)g_xHi)[idx] = h;
    ((uint2*)g_xLo)[idx] = l;
}

// ---------------------------------------------------------------------------
// Conv weight split + transpose: g_cwHi/Lo[l][co][k=tap*128+ci]
// ---------------------------------------------------------------------------
__global__ void cwsplit_kernel(const float* __restrict__ cw) {
    int idx = blockIdx.x * 256 + threadIdx.x;
    if (idx >= N_CONV*128*512) return;
    int l   = idx / (128*512);
    int rem = idx - l*128*512;
    int co  = rem >> 9;
    int k   = rem & 511;
    int tap = k >> 7;
    int ci  = k & 127;
    float v = cw[((l*128 + co)*128 + ci)*4 + tap];
    __nv_bfloat16 h = __float2bfloat16(v);
    g_cwHi[idx] = h;
    g_cwLo[idx] = __float2bfloat16(v - __bfloat162float(h));
}

// ---------------------------------------------------------------------------
// Expert weight split + transpose: g_wtHi/Lo[e][f][d]
// ---------------------------------------------------------------------------
__global__ void wsplit_kernel(const float* __restrict__ ew) {
    int idx = blockIdx.x * 256 + threadIdx.x;
    if (idx >= N_EXPERTS*128*128) return;
    int e = idx / 16384;
    int rem = idx - e*16384;
    int d = rem >> 7;
    int f = rem & 127;
    float v = ew[idx];
    __nv_bfloat16 h = __float2bfloat16(v);
    g_wtHi[e*16384 + f*128 + d] = h;
    g_wtLo[e*16384 + f*128 + d] = __float2bfloat16(v - __bfloat162float(h));
}

// ---------------------------------------------------------------------------
// Conv layer via mma.sync split-bf16.
// Per CTA: 64 patch rows x 128 co, K=512 in 8 chunks of 64, cp.async
// double-buffered. 8 warps (2x4), warp tile 32x32.
// Epilogue: bias+BN+leaky fused; output written as split hi/lo bf16.
// ---------------------------------------------------------------------------
#define STR2 72
#define CV_A(db, hl)  ((uint32_t)(((db)*2+(hl)) * 9216))
#define CV_B(db, hl)  ((uint32_t)(36864 + ((db)*2+(hl)) * 18432))
#define CV_ROWOFF     110592u
#define CV_BN         111616u
#define CV_SMEM       112640u

__device__ __forceinline__ void conv_issue_chunk(
    uint32_t smb, char* dsm, int db, int chunk,
    const __nv_bfloat16* __restrict__ inHi,
    const __nv_bfloat16* __restrict__ inLo,
    int l, int tid)
{
    const int tap = chunk >> 1;
    const int ciB = (chunk & 1) * 64;
    const int* rowOffS = (const int*)(dsm + CV_ROWOFF);
    // A: 1024 uint4 (hi 512 + lo 512), 64 rows x 64 k
    #pragma unroll
    for (int j = 0; j < 4; ++j) {
        int i   = tid + j*256;
        int buf = i >> 9;
        int rem = i & 511;
        int r   = rem >> 3, c8 = rem & 7;
        const __nv_bfloat16* src = (buf ? inLo : inHi) + rowOffS[r*4 + tap] + ciB + c8*8;
        uint32_t dst = smb + CV_A(db, buf) + (uint32_t)(r*STR2 + c8*8)*2u;
        CP_ASYNC16(dst, src);
    }
    // B: 2048 uint4 (hi 1024 + lo 1024), 128 co x 64 k
    #pragma unroll
    for (int j = 0; j < 8; ++j) {
        int i   = tid + j*256;
        int buf = i >> 10;
        int rem = i & 1023;
        int n   = rem >> 3, c8 = rem & 7;
        const __nv_bfloat16* src = (buf ? g_cwLo : g_cwHi)
                                 + (size_t)(l*128 + n)*512 + chunk*64 + c8*8;
        uint32_t dst = smb + CV_B(db, buf) + (uint32_t)(n*STR2 + c8*8)*2u;
        CP_ASYNC16(dst, src);
    }
    CP_COMMIT();
}

__global__ __launch_bounds__(256)
void conv_mma_kernel(const __nv_bfloat16* __restrict__ inHi,
                     const __nv_bfloat16* __restrict__ inLo,
                     __nv_bfloat16* __restrict__ outHi,
                     __nv_bfloat16* __restrict__ outLo,
                     int Si, int So, int M, int l,
                     const float* __restrict__ cb,
                     const float* __restrict__ gma,
                     const float* __restrict__ bta,
                     const float* __restrict__ mu,
                     const float* __restrict__ var) {
    extern __shared__ char dsm[];
    const uint32_t smb = smem_u32(dsm);

    const int tid  = threadIdx.x;
    const int wid  = tid >> 5;
    const int lane = tid & 31;
    const int g    = lane >> 2;
    const int t    = lane & 3;
    const int warp_m = wid & 1;
    const int warp_n = wid >> 1;
    const int pm0  = blockIdx.x * 64;

    int*   rowOffS = (int*)(dsm + CV_ROWOFF);
    float* aCs     = (float*)(dsm + CV_BN);
    float* cCs     = aCs + 128;

    // rowOff: 64 rows x 4 taps (one entry per thread)
    {
        int r = tid >> 2, tap = tid & 3;
        int p = pm0 + r; if (p > M-1) p = M-1;
        int sq = So * So;
        int n  = p / sq;
        int rm = p - n*sq;
        int y  = rm / So;
        int xx = rm - y*So;
        int ky = tap >> 1, kx = tap & 1;
        rowOffS[r*4 + tap] = ((n*Si + 2*y + ky)*Si + (2*xx + kx)) * 128;
    }
    if (tid < 128) {
        float a = gma[tid] * rsqrtf(var[tid] + BN_EPS);
        aCs[tid] = a;
        cCs[tid] = a * (cb[tid] - mu[tid]) + bta[tid];
    }
    __syncthreads();

    conv_issue_chunk(smb, dsm, 0, 0, inHi, inLo, l, tid);

    float acc[2][4][4];
    #pragma unroll
    for (int mt = 0; mt < 2; ++mt)
        #pragma unroll
        for (int nt = 0; nt < 4; ++nt)
            #pragma unroll
            for (int j = 0; j < 4; ++j) acc[mt][nt][j] = 0.f;

    for (int c = 0; c < 8; ++c) {
        if (c < 7) {
            conv_issue_chunk(smb, dsm, (c+1)&1, c+1, inHi, inLo, l, tid);
            CP_WAIT(1);
        } else {
            CP_WAIT(0);
        }
        __syncthreads();

        const int db = c & 1;
        const __nv_bfloat16* Ahi = (const __nv_bfloat16*)(dsm + CV_A(db,0));
        const __nv_bfloat16* Alo = (const __nv_bfloat16*)(dsm + CV_A(db,1));
        const __nv_bfloat16* Bhi = (const __nv_bfloat16*)(dsm + CV_B(db,0));
        const __nv_bfloat16* Blo = (const __nv_bfloat16*)(dsm + CV_B(db,1));

        #pragma unroll
        for (int term = 0; term < 3; ++term) {
            const __nv_bfloat16* Ab = (term == 1) ? Alo : Ahi;
            const __nv_bfloat16* Bf = (term == 2) ? Blo : Bhi;
            #pragma unroll
            for (int ks = 0; ks < 4; ++ks) {
                const int k0 = ks*16;
                uint32_t af[2][4];
                #pragma unroll
                for (int mt = 0; mt < 2; ++mt) {
                    int r0 = warp_m*32 + mt*16 + g;
                    const __nv_bfloat16* ap = Ab + k0 + 2*t;
                    af[mt][0] = *(const uint32_t*)(ap + (size_t)r0*STR2);
                    af[mt][1] = *(const uint32_t*)(ap + (size_t)(r0+8)*STR2);
                    af[mt][2] = *(const uint32_t*)(ap + (size_t)r0*STR2 + 8);
                    af[mt][3] = *(const uint32_t*)(ap + (size_t)(r0+8)*STR2 + 8);
                }
                #pragma unroll
                for (int nt = 0; nt < 4; ++nt) {
                    int n = warp_n*32 + nt*8 + g;
                    const __nv_bfloat16* bp = Bf + (size_t)n*STR2 + k0 + 2*t;
                    uint32_t b0 = *(const uint32_t*)bp;
                    uint32_t b1 = *(const uint32_t*)(bp + 8);
                    mma16816(acc[0][nt], af[0], b0, b1);
                    mma16816(acc[1][nt], af[1], b0, b1);
                }
            }
        }
        __syncthreads();
    }

    // Epilogue: bias+BN+leaky, split to hi/lo bf16, store
    uint32_t* oHi = (uint32_t*)outHi;
    uint32_t* oLo = (uint32_t*)outLo;
    #pragma unroll
    for (int mt = 0; mt < 2; ++mt) {
        int r0 = pm0 + warp_m*32 + mt*16 + g;
        #pragma unroll
        for (int nt = 0; nt < 4; ++nt) {
            int col = warp_n*32 + nt*8 + 2*t;
            float a0 = aCs[col], a1 = aCs[col+1];
            float c0 = cCs[col], c1 = cCs[col+1];
            float v00 = acc[mt][nt][0]*a0 + c0; v00 = v00 > 0.f ? v00 : 0.2f*v00;
            float v01 = acc[mt][nt][1]*a1 + c1; v01 = v01 > 0.f ? v01 : 0.2f*v01;
            float v10 = acc[mt][nt][2]*a0 + c0; v10 = v10 > 0.f ? v10 : 0.2f*v10;
            float v11 = acc[mt][nt][3]*a1 + c1; v11 = v11 > 0.f ? v11 : 0.2f*v11;
            if (r0 < M) {
                __nv_bfloat16 h0 = __float2bfloat16(v00);
                __nv_bfloat16 h1 = __float2bfloat16(v01);
                uint32_t hw = (uint32_t)__bfloat16_as_ushort(h0)
                            | ((uint32_t)__bfloat16_as_ushort(h1) << 16);
                uint32_t lw = pack_bf16(v00 - __bfloat162float(h0),
                                        v01 - __bfloat162float(h1));
                oHi[r0*64 + (col>>1)] = hw;
                oLo[r0*64 + (col>>1)] = lw;
            }
            if (r0 + 8 < M) {
                __nv_bfloat16 h0 = __float2bfloat16(v10);
                __nv_bfloat16 h1 = __float2bfloat16(v11);
                uint32_t hw = (uint32_t)__bfloat16_as_ushort(h0)
                            | ((uint32_t)__bfloat16_as_ushort(h1) << 16);
                uint32_t lw = pack_bf16(v10 - __bfloat162float(h0),
                                        v11 - __bfloat162float(h1));
                oHi[(r0+8)*64 + (col>>1)] = hw;
                oLo[(r0+8)*64 + (col>>1)] = lw;
            }
        }
    }
}

// ---------------------------------------------------------------------------
// Gates kernel (reads split conv output, reconstructs fp32)
// ---------------------------------------------------------------------------
__global__ void gates_kernel(const __nv_bfloat16* __restrict__ zfHi,
                             const __nv_bfloat16* __restrict__ zfLo,
                             const float* __restrict__ fw,
                             const float* __restrict__ fb,
                             const float* __restrict__ wg) {
    __shared__ float s_s[96];
    __shared__ float s_amp[Bb][NUM_FREQS];
    __shared__ float s_log[Bb][N_EXPERTS];

    const int tid  = threadIdx.x;
    const int lane = tid & 31;
    const int warp = tid >> 5;

    for (int r = warp; r < 96; r += 4) {
        float v = 0.f;
        #pragma unroll
        for (int j = 0; j < 4; ++j) {
            int c = lane + j*32;
            float z = __bfloat162float(zfHi[r*128 + c]) + __bfloat162float(zfLo[r*128 + c]);
            v += z * fw[c];
        }
        #pragma unroll
        for (int off = 16; off; off >>= 1)
            v += __shfl_down_sync(0xffffffffu, v, off);
        if (lane == 0) s_s[r] = v + fb[0];
    }
    __syncthreads();

    if (tid < Bb*NUM_FREQS) {
        int b = tid / NUM_FREQS;
        int k = tid % NUM_FREQS + 1;
        float re = 0.f, im = 0.f;
        #pragma unroll
        for (int t = 0; t < Tt; ++t) {
            int m = (k * t) % 24;
            float ang = -(float)M_PI * (float)m / 12.f;
            float sv, cv;
            sincosf(ang, &sv, &cv);
            float x = s_s[b*Tt + t];
            re += x * cv;
            im += x * sv;
        }
        s_amp[b][k-1] = sqrtf(re*re + im*im) * 0.2041241452319315f;
    }
    __syncthreads();

    if (tid < Bb*N_EXPERTS) {
        int b = tid / N_EXPERTS;
        int e = tid % N_EXPERTS;
        float l = 0.f;
        #pragma unroll
        for (int k = 0; k < NUM_FREQS; ++k)
            l += s_amp[b][k] * wg[k*N_EXPERTS + e];
        s_log[b][e] = l;
    }
    __syncthreads();

    if (tid < Bb) {
        int b = tid;
        int i1 = 0; float v1 = s_log[b][0];
        #pragma unroll
        for (int e = 1; e < N_EXPERTS; ++e)
            if (s_log[b][e] > v1) { v1 = s_log[b][e]; i1 = e; }
        int i2 = -1; float v2 = -INFINITY;
        #pragma unroll
        for (int e = 0; e < N_EXPERTS; ++e)
            if (e != i1 && s_log[b][e] > v2) { v2 = s_log[b][e]; i2 = e; }
        float e1 = expf(v2 - v1);
        float den = 1.f + e1;
        g_gates[b*2 + 0] = 1.f / den;
        g_gates[b*2 + 1] = e1 / den;
        g_eidx [b*2 + 0] = i1;
        g_eidx [b*2 + 1] = i2;
    }
}

// ---------------------------------------------------------------------------
// MoE main path via mma.sync bf16 (split hi/lo, 3 terms per expert).
// A now pre-split in global (g_xHi/g_xLo) -> pure smem copy.
// ---------------------------------------------------------------------------
#define STR   136
#define SA_HI 0
#define SA_LO 17408
#define SB_HI 34816
#define SB_LO 69632
#define MOE_SMEM 104448

__global__ __launch_bounds__(256)
void moe_mma_kernel(const float* __restrict__ eb,
                    float* __restrict__ out) {
    extern __shared__ char dsm[];
    __nv_bfloat16* sAhi = (__nv_bfloat16*)(dsm + SA_HI);
    __nv_bfloat16* sAlo = (__nv_bfloat16*)(dsm + SA_LO);
    __nv_bfloat16* sBhi = (__nv_bfloat16*)(dsm + SB_HI);
    __nv_bfloat16* sBlo = (__nv_bfloat16*)(dsm + SB_LO);

    const int tid  = threadIdx.x;
    const int wid  = tid >> 5;
    const int lane = tid & 31;
    const int g    = lane >> 2;
    const int t    = lane & 3;
    const int warp_m = wid & 1;
    const int warp_n = wid >> 1;
    const int pm0  = blockIdx.x * 64;
    const int b    = pm0 / NPOS_PER_B;

    // --- A: copy pre-split x (2048 uint4: hi 1024 + lo 1024) ------------------
    #pragma unroll
    for (int j = 0; j < 8; ++j) {
        int i   = tid + j*256;
        int buf = i >> 10;
        int rem = i & 1023;
        int r   = rem >> 4, c16 = rem & 15;
        const __nv_bfloat16* src = (buf ? g_xLo : g_xHi)
                                 + (size_t)(pm0 + r)*128 + c16*8;
        uint4 v = *(const uint4*)src;
        __nv_bfloat16* dstb = buf ? sAlo : sAhi;
        *(uint4*)&dstb[r*STR + c16*8] = v;
    }

    float comb[2][4][4];
    #pragma unroll
    for (int mt = 0; mt < 2; ++mt)
        #pragma unroll
        for (int nt = 0; nt < 4; ++nt)
            #pragma unroll
            for (int j = 0; j < 4; ++j) comb[mt][nt][j] = 0.f;

    #pragma unroll
    for (int s = 0; s < 2; ++s) {
        const int   e  = g_eidx[b*2 + s];
        const float gv = g_gates[b*2 + s];

        __syncthreads();
        #pragma unroll
        for (int j = 0; j < 16; ++j) {
            int i   = tid + j*256;
            int buf = i >> 11;
            int rem = i & 2047;
            int n   = rem >> 4;
            int c   = i & 15;
            const __nv_bfloat16* src = (buf ? g_wtLo : g_wtHi) + e*16384 + n*128 + c*8;
            uint4 v = *(const uint4*)src;
            __nv_bfloat16* dstb = buf ? sBlo : sBhi;
            *(uint4*)&dstb[n*STR + c*8] = v;
        }
        __syncthreads();

        float acc[2][4][4];
        #pragma unroll
        for (int mt = 0; mt < 2; ++mt)
            #pragma unroll
            for (int nt = 0; nt < 4; ++nt)
                #pragma unroll
                for (int j = 0; j < 4; ++j) acc[mt][nt][j] = 0.f;

        #pragma unroll
        for (int term = 0; term < 3; ++term) {
            const __nv_bfloat16* Ab = (term == 1) ? sAlo : sAhi;
            const __nv_bfloat16* Bbuf = (term == 2) ? sBlo : sBhi;
            #pragma unroll
            for (int ks = 0; ks < 8; ++ks) {
                const int k0 = ks*16;
                uint32_t af[2][4];
                #pragma unroll
                for (int mt = 0; mt < 2; ++mt) {
                    int r0 = warp_m*32 + mt*16 + g;
                    const __nv_bfloat16* ap = Ab + k0 + 2*t;
                    af[mt][0] = *(const uint32_t*)(ap + (size_t)r0*STR);
                    af[mt][1] = *(const uint32_t*)(ap + (size_t)(r0+8)*STR);
                    af[mt][2] = *(const uint32_t*)(ap + (size_t)r0*STR + 8);
                    af[mt][3] = *(const uint32_t*)(ap + (size_t)(r0+8)*STR + 8);
                }
                #pragma unroll
                for (int nt = 0; nt < 4; ++nt) {
                    int n = warp_n*32 + nt*8 + g;
                    const __nv_bfloat16* bp = Bbuf + (size_t)n*STR + k0 + 2*t;
                    uint32_t b0 = *(const uint32_t*)bp;
                    uint32_t b1 = *(const uint32_t*)(bp + 8);
                    mma16816(acc[0][nt], af[0], b0, b1);
                    mma16816(acc[1][nt], af[1], b0, b1);
                }
            }
        }

        #pragma unroll
        for (int nt = 0; nt < 4; ++nt) {
            int col0 = warp_n*32 + nt*8 + 2*t;
            float b0v = eb[e*128 + col0];
            float b1v = eb[e*128 + col0 + 1];
            #pragma unroll
            for (int mt = 0; mt < 2; ++mt) {
                comb[mt][nt][0] += gv * expf(acc[mt][nt][0] + b0v);
                comb[mt][nt][1] += gv * expf(acc[mt][nt][1] + b1v);
                comb[mt][nt][2] += gv * expf(acc[mt][nt][2] + b0v);
                comb[mt][nt][3] += gv * expf(acc[mt][nt][3] + b1v);
            }
        }
    }

    #pragma unroll
    for (int mt = 0; mt < 2; ++mt) {
        int row = pm0 + warp_m*32 + mt*16 + g;
        #pragma unroll
        for (int nt = 0; nt < 4; ++nt) {
            int col = warp_n*32 + nt*8 + 2*t;
            float c0 = comb[mt][nt][0]; if (c0 == 0.f) c0 = COMBINE_EPS;
            float c1 = comb[mt][nt][1]; if (c1 == 0.f) c1 = COMBINE_EPS;
            float c2 = comb[mt][nt][2]; if (c2 == 0.f) c2 = COMBINE_EPS;
            float c3 = comb[mt][nt][3]; if (c3 == 0.f) c3 = COMBINE_EPS;
            float2 o0 = make_float2(logf(c0), logf(c1));
            float2 o1 = make_float2(logf(c2), logf(c3));
            *(float2*)&out[(size_t)row*128 + col]      = o0;
            *(float2*)&out[(size_t)(row+8)*128 + col]  = o1;
        }
    }
}

// ---------------------------------------------------------------------------
// Launch
// ---------------------------------------------------------------------------
extern "C" void kernel_launch(void* const* d_in, const int* in_sizes, int n_in,
                              void* d_out, int out_size) {
    const float* x        = (const float*)d_in[0];
    const float* conv_w   = (const float*)d_in[1];
    const float* conv_b   = (const float*)d_in[2];
    const float* bn_gamma = (const float*)d_in[3];
    const float* bn_beta  = (const float*)d_in[4];
    const float* bn_mean  = (const float*)d_in[5];
    const float* bn_var   = (const float*)d_in[6];
    const float* fuse_w   = (const float*)d_in[7];
    const float* fuse_b   = (const float*)d_in[8];
    const float* w_gate   = (const float*)d_in[9];
    const float* expert_w = (const float*)d_in[10];
    const float* expert_b = (const float*)d_in[11];
    float* out = (float*)d_out;

    __nv_bfloat16 *xHi, *xLo, *aHi0, *aLo0, *aHi1, *aLo1;
    cudaGetSymbolAddress((void**)&xHi,  g_xHi);
    cudaGetSymbolAddress((void**)&xLo,  g_xLo);
    cudaGetSymbolAddress((void**)&aHi0, g_aHi0);
    cudaGetSymbolAddress((void**)&aLo0, g_aLo0);
    cudaGetSymbolAddress((void**)&aHi1, g_aHi1);
    cudaGetSymbolAddress((void**)&aLo1, g_aLo1);

    cudaFuncSetAttribute(conv_mma_kernel,
                         cudaFuncAttributeMaxDynamicSharedMemorySize, CV_SMEM);
    cudaFuncSetAttribute(moe_mma_kernel,
                         cudaFuncAttributeMaxDynamicSharedMemorySize, MOE_SMEM);

    xsplit_kernel<<<(NPOS_TOTAL*32 + 255)/256, 256>>>((const float4*)x);
    cwsplit_kernel<<<(N_CONV*128*512 + 255)/256, 256>>>(conv_w);
    wsplit_kernel<<<(N_EXPERTS*128*128 + 255)/256, 256>>>(expert_w);

    // conv layers: in/out split buffers alternate
    const __nv_bfloat16* iH = xHi;
    const __nv_bfloat16* iL = xLo;
    int Si = 32;
    for (int l = 0; l < N_CONV; ++l) {
        int So = Si >> 1;
        int M  = 96 * So * So;
        __nv_bfloat16* oH = (l & 1) ? aHi1 : aHi0;
        __nv_bfloat16* oL = (l & 1) ? aLo1 : aLo0;
        int grid = (M + 63) / 64;
        conv_mma_kernel<<<grid, 256, CV_SMEM>>>(iH, iL, oH, oL, Si, So, M, l,
                                                conv_b   + l*128,
                                                bn_gamma + l*128,
                                                bn_beta  + l*128,
                                                bn_mean  + l*128,
                                                bn_var   + l*128);
        iH = oH; iL = oL;
        Si = So;
    }
    // last layer (l=4) wrote buf0

    gates_kernel<<<1, 128>>>(aHi0, aLo0, fuse_w, fuse_b, w_gate);

    moe_mma_kernel<<<NPOS_TOTAL/64, 256, MOE_SMEM>>>(expert_b, out);
}